// round 16
// baseline (speedup 1.0000x reference)
#include <cuda_runtime.h>
#include <cuda_bf16.h>
#include <cstdint>

// ---------------- problem constants ----------------
#define BROWS   65536
#define DDIM    1024
#define NCOLS   128      // 120 real columns padded to 128
#define KC      64       // K elems staged per chunk
#define NCHUNK  (DDIM / KC)   // 16
#define TILE_M  128
#define APITCH  80       // int8 smem row pitch (bytes): conflict-free ldmatrix
#define OPAD    130      // out-tile row pitch (floats)

#define ABYTES  (TILE_M * APITCH)       // 10240 per A stage (int8)
#define BOFF2   (2 * ABYTES)            // 20480
#define SMEM_BYTES (TILE_M * OPAD * 4)  // 66560 (>= 4*10240 stage ring)

#define SX_STEP (5.0f / 127.0f)
#define INV_SX  (127.0f / 5.0f)

// packed weights: [NCOLS][DDIM] int8, per-column scaled. rows 120..127 stay zero.
__device__ __align__(16) int8_t g_Wpack[NCOLS * DDIM];
__device__ float g_scale[NCOLS];   // = colmax/127 * SX_STEP; 120..127 zero

__device__ __forceinline__ uint32_t smem_u32(const void* p) {
    uint32_t a;
    asm("{ .reg .u64 t; cvta.to.shared.u64 t, %1; cvt.u32.u64 %0, t; }" : "=r"(a) : "l"(p));
    return a;
}
#define CP_ASYNC16(dst_u32, src_ptr) \
    asm volatile("cp.async.cg.shared.global [%0], [%1], 16;" :: "r"(dst_u32), "l"(src_ptr) : "memory")
#define CP_COMMIT() asm volatile("cp.async.commit_group;" ::: "memory")
#define CP_WAIT0()  asm volatile("cp.async.wait_group 0;" ::: "memory")
#define LDSM_X4(r, addr) \
    asm volatile("ldmatrix.sync.aligned.m8n8.x4.shared.b16 {%0,%1,%2,%3}, [%4];" \
                 : "=r"((r)[0]), "=r"((r)[1]), "=r"((r)[2]), "=r"((r)[3]) : "r"(addr))
#define IMMA(d, a, b0_, b1_) \
    asm volatile("mma.sync.aligned.m16n8k32.row.col.s32.s8.s8.s32 " \
                 "{%0,%1,%2,%3}, {%4,%5,%6,%7}, {%8,%9}, {%0,%1,%2,%3};" \
                 : "+r"((d)[0]), "+r"((d)[1]), "+r"((d)[2]), "+r"((d)[3]) \
                 : "r"((a)[0]), "r"((a)[1]), "r"((a)[2]), "r"((a)[3]), "r"(b0_), "r"(b1_))

// quantize 4 floats -> packed s8x4 (byte0 = first value)
__device__ __forceinline__ uint32_t quant4(float4 v) {
    int q0 = __float2int_rn(v.x * INV_SX);
    int q1 = __float2int_rn(v.y * INV_SX);
    int q2 = __float2int_rn(v.z * INV_SX);
    int q3 = __float2int_rn(v.w * INV_SX);
    uint32_t t, pk;
    asm("cvt.pack.sat.s8.s32.b32 %0, %1, %2, %3;" : "=r"(t)  : "r"(q3), "r"(q2), "r"(0));
    asm("cvt.pack.sat.s8.s32.b32 %0, %1, %2, %3;" : "=r"(pk) : "r"(q1), "r"(q0), "r"(t));
    return pk;
}

// ---------------- weight pack kernel: per-column int8 quant + scale ----------
// grid 120 blocks x 256 thr; block j handles output column j.
__global__ void pack_weights_int8(const float* __restrict__ expert_w,
                                  const float* __restrict__ gate_w) {
    __shared__ float smax[8];
    const int j = blockIdx.x;
    const int tid = threadIdx.x;
    const float* src;
    if (j < 100) {
        src = expert_w + (size_t)(j / 10) * DDIM * 10 + (j % 10);
    } else {
        src = gate_w + (size_t)((j - 100) / 10) * DDIM * 10 + ((j - 100) % 10);
    }
    float v[4]; float m = 0.0f;
    #pragma unroll
    for (int i = 0; i < 4; ++i) {
        v[i] = src[(size_t)(tid + i * 256) * 10];
        m = fmaxf(m, fabsf(v[i]));
    }
    #pragma unroll
    for (int o = 16; o; o >>= 1) m = fmaxf(m, __shfl_xor_sync(~0u, m, o));
    if ((tid & 31) == 0) smax[tid >> 5] = m;
    __syncthreads();
    if (tid < 32) {
        float t2 = (tid < 8) ? smax[tid] : 0.0f;
        #pragma unroll
        for (int o = 4; o; o >>= 1) t2 = fmaxf(t2, __shfl_xor_sync(~0u, t2, o));
        if (tid == 0) smax[0] = t2;
    }
    __syncthreads();
    const float mx = fmaxf(smax[0], 1e-30f);
    const float inv = 127.0f / mx;
    #pragma unroll
    for (int i = 0; i < 4; ++i) {
        int q = __float2int_rn(v[i] * inv);
        q = max(-127, min(127, q));
        g_Wpack[(size_t)j * DDIM + tid + i * 256] = (int8_t)q;
    }
    if (tid == 0) g_scale[j] = (mx / 127.0f) * SX_STEP;
}

// ---------------- fused MMoE main kernel (int8 IMMA, 128x128 tile) -----------
extern "C" __global__ void __launch_bounds__(256, 2)
mmoe_main_kernel(const float* __restrict__ x,
                 const float* __restrict__ expert_b,   // [10,10]
                 const float* __restrict__ gate_b,     // [2,10]
                 const float* __restrict__ ctr_w,      // [10]
                 const float* __restrict__ ctr_b,      // [1]
                 const float* __restrict__ cvr_w,      // [10]
                 const float* __restrict__ cvr_b,      // [1]
                 float* __restrict__ out) {            // [2*B] = [ctr | cvr]
    extern __shared__ char smem[];
    const uint32_t smem_base = smem_u32(smem);
    float* outS = reinterpret_cast<float*>(smem);

    const int tid  = threadIdx.x;
    const int wid  = tid >> 5;
    const int lane = tid & 31;
    const int gid  = lane >> 2;
    const int tig  = lane & 3;
    const int warp_m = (wid & 3) * 32;    // 4 warps along M
    const int warp_n = (wid >> 2) * 64;   // 2 warps along N
    const int row0 = blockIdx.x * TILE_M;
    const int wstag = wid & 1;            // 2-phase k stagger

    // ldmatrix bases (int8 tiles read as b16 matrices — fragments match s8 MMA)
    const uint32_t aLdsmBase =
        (uint32_t)(warp_m + ((lane >> 3) & 1) * 8 + (lane & 7)) * APITCH
        + ((lane >> 4) & 1) * 16;
    const uint32_t bLdsmBase =
        (uint32_t)(warp_n + ((lane >> 4) & 1) * 8 + (lane & 7)) * APITCH
        + ((lane >> 3) & 1) * 16;

    const int rbase = tid >> 4;          // A rows rbase + it*16 (it<8)
    const int c4    = tid & 15;          // float4 col index

    int acc[2][8][4];
    #pragma unroll
    for (int mt = 0; mt < 2; ++mt)
        #pragma unroll
        for (int nt = 0; nt < 8; ++nt)
            #pragma unroll
            for (int i = 0; i < 4; ++i) acc[mt][nt][i] = 0;

    float4 av[8];

    auto ldgA = [&](int c) {
        const int k0 = c * KC;
        #pragma unroll
        for (int it = 0; it < 8; ++it)
            av[it] = *reinterpret_cast<const float4*>(
                x + (size_t)(row0 + rbase + it * 16) * DDIM + k0 + c4 * 4);
    };
    auto stsA = [&](int c) {             // quantize av -> int8 A buffer (c&1)
        int8_t* Ab = reinterpret_cast<int8_t*>(smem + (c & 1) * ABYTES);
        #pragma unroll
        for (int it = 0; it < 8; ++it) {
            uint32_t pk = quant4(av[it]);
            *reinterpret_cast<uint32_t*>(Ab + (rbase + it * 16) * APITCH + c4 * 4) = pk;
        }
    };
    auto issue_B = [&](int c) {          // cp.async int8 B chunk (64B/row)
        const int k0 = c * KC;
        const uint32_t bb = smem_base + BOFF2 + (c & 1) * ABYTES;
        #pragma unroll
        for (int it = 0; it < 2; ++it) {
            const int idx = tid + it * 256;          // 0..511
            const int row = idx >> 2, g = idx & 3;
            CP_ASYNC16(bb + (uint32_t)(row * APITCH + g * 16),
                       g_Wpack + (size_t)row * DDIM + k0 + g * 16);
        }
        CP_COMMIT();
    };

    // ---- prologue ----
    ldgA(0);
    issue_B(0);

    for (int c = 0; c < NCHUNK; ++c) {
        stsA(c);                          // av holds A(c); buffer (c&1) free (barrier c-1)
        if (c + 1 < NCHUNK) ldgA(c + 1);
        CP_WAIT0();                       // B(c) landed (overlapped compute(c-1))
        __syncthreads();                  // A(c)/B(c) visible; compute(c-1) retired
        if (c + 1 < NCHUNK) issue_B(c + 1);

        const uint32_t aStage = smem_base + (c & 1) * ABYTES;
        const uint32_t bStage = smem_base + BOFF2 + (c & 1) * ABYTES;

        #pragma unroll
        for (int j = 0; j < 2; ++j) {     // 2 k-tiles of 32, warp-staggered
            const uint32_t kOff = (uint32_t)(((j + wstag) & 1) << 5);

            uint32_t afrag[2][4];
            #pragma unroll
            for (int mt = 0; mt < 2; ++mt)
                LDSM_X4(afrag[mt],
                        aStage + aLdsmBase + (uint32_t)(mt * 16 * APITCH) + kOff);

            #pragma unroll
            for (int pr = 0; pr < 4; ++pr) {
                uint32_t bfr[4];
                LDSM_X4(bfr, bStage + bLdsmBase + (uint32_t)(pr * 16 * APITCH) + kOff);
                #pragma unroll
                for (int mt = 0; mt < 2; ++mt) {
                    IMMA(acc[mt][2 * pr],     afrag[mt], bfr[0], bfr[1]);
                    IMMA(acc[mt][2 * pr + 1], afrag[mt], bfr[2], bfr[3]);
                }
            }
        }
    }
    __syncthreads();   // IMMAs done; stage ring dead -> reuse smem as outS

    // --- scatter accumulators (descaled) to fp32 out tile ---
    #pragma unroll
    for (int mt = 0; mt < 2; ++mt) {
        #pragma unroll
        for (int nt = 0; nt < 8; ++nt) {
            const int r = warp_m + mt * 16 + gid;
            const int col = warp_n + nt * 8 + tig * 2;
            const float s0 = g_scale[col], s1 = g_scale[col + 1];
            *reinterpret_cast<float2*>(outS + r * OPAD + col) =
                make_float2((float)acc[mt][nt][0] * s0, (float)acc[mt][nt][1] * s1);
            *reinterpret_cast<float2*>(outS + (r + 8) * OPAD + col) =
                make_float2((float)acc[mt][nt][2] * s0, (float)acc[mt][nt][3] * s1);
        }
    }
    __syncthreads();

    // --- per-row epilogue: softmax gates, expert mix, sigmoid heads ---
    if (tid < TILE_M) {
        const float* rowv = outS + tid * OPAD;

        float g[2][10];
        #pragma unroll
        for (int t = 0; t < 2; ++t) {
            float s = 0.0f;
            #pragma unroll
            for (int e = 0; e < 10; ++e) {
                float l = rowv[100 + t * 10 + e] + gate_b[t * 10 + e];
                float ex = expf(l);
                g[t][e] = ex; s += ex;
            }
            float inv = 1.0f / s;
            #pragma unroll
            for (int e = 0; e < 10; ++e) g[t][e] *= inv;
        }

        float ti0[10], ti1[10];
        #pragma unroll
        for (int u = 0; u < 10; ++u) { ti0[u] = 0.0f; ti1[u] = 0.0f; }
        #pragma unroll
        for (int e = 0; e < 10; ++e) {
            const float g0 = g[0][e], g1 = g[1][e];
            #pragma unroll
            for (int u = 0; u < 10; ++u) {
                const int j = e * 10 + u;
                float v = fmaxf(rowv[j] + expert_b[j], 0.0f);
                ti0[u] += v * g0;
                ti1[u] += v * g1;
            }
        }

        float zc = ctr_b[0], zv = cvr_b[0];
        #pragma unroll
        for (int u = 0; u < 10; ++u) {
            zc += ti0[u] * ctr_w[u];
            zv += ti1[u] * cvr_w[u];
        }
        const int gr = row0 + tid;
        out[gr]         = 1.0f / (1.0f + expf(-zc));
        out[BROWS + gr] = 1.0f / (1.0f + expf(-zv));
    }
}

// ---------------- launch ----------------
extern "C" void kernel_launch(void* const* d_in, const int* in_sizes, int n_in,
                              void* d_out, int out_size) {
    const float* x        = (const float*)d_in[0];
    const float* expert_w = (const float*)d_in[3];
    const float* expert_b = (const float*)d_in[4];
    const float* gate_w   = (const float*)d_in[5];
    const float* gate_b   = (const float*)d_in[6];
    const float* ctr_w    = (const float*)d_in[7];
    const float* ctr_b    = (const float*)d_in[8];
    const float* cvr_w    = (const float*)d_in[9];
    const float* cvr_b    = (const float*)d_in[10];
    float* out = (float*)d_out;

    cudaFuncSetAttribute(mmoe_main_kernel,
                         cudaFuncAttributeMaxDynamicSharedMemorySize, SMEM_BYTES);

    pack_weights_int8<<<120, 256>>>(expert_w, gate_w);
    mmoe_main_kernel<<<BROWS / TILE_M, 256, SMEM_BYTES>>>(
        x, expert_b, gate_b, ctr_w, ctr_b, cvr_w, cvr_b, out);
}

// round 17
// speedup vs baseline: 2.0780x; 2.0780x over previous
#include <cuda_runtime.h>
#include <cuda_bf16.h>
#include <cstdint>

// ---------------- problem constants ----------------
#define BROWS   65536
#define DDIM    1024
#define NCOLS   128      // 120 real columns padded to 128
#define KC      64       // K elems staged per chunk
#define NCHUNK  (DDIM / KC)   // 16
#define TILE_M  128
#define APAD    72       // smem row pitch (bf16): 144B rows -> conflict-free LDSM
#define OPAD    130      // out-tile row pitch (floats)

#define ABYTES  (TILE_M * APAD * 2)     // 18432 per A buffer
#define BOFF    (2 * ABYTES)            // 36864
#define BBYTES  (NCOLS * APAD * 2)      // 18432 per B buffer
#define SMEM_BYTES (BOFF + 2 * BBYTES)  // 73728 (>= out tile 128*130*4=66560)

// packed weights: [NCOLS][DDIM] K-major bf16 (static device array — no alloc)
// rows 120..127 never written: __device__ globals are zero-initialized.
__device__ __align__(16) __nv_bfloat16 g_Wpack[NCOLS * DDIM];

__device__ __forceinline__ uint32_t smem_u32(const void* p) {
    uint32_t a;
    asm("{ .reg .u64 t; cvta.to.shared.u64 t, %1; cvt.u32.u64 %0, t; }" : "=r"(a) : "l"(p));
    return a;
}
#define CP_ASYNC16(dst_u32, src_ptr) \
    asm volatile("cp.async.cg.shared.global [%0], [%1], 16;" :: "r"(dst_u32), "l"(src_ptr) : "memory")
#define CP_COMMIT() asm volatile("cp.async.commit_group;" ::: "memory")
#define CP_WAIT0()  asm volatile("cp.async.wait_group 0;" ::: "memory")
#define LDSM_X4(r0, r1, r2, r3, addr) \
    asm volatile("ldmatrix.sync.aligned.m8n8.x4.shared.b16 {%0,%1,%2,%3}, [%4];" \
                 : "=r"(r0), "=r"(r1), "=r"(r2), "=r"(r3) : "r"(addr))

// ---------------- weight pack kernel (smem transpose, both sides coalesced) ----
// grid (12, 4) x 256 thr.  bx<10: expert e=bx;  bx 10,11: gate t=bx-10.
__global__ void pack_weights_kernel(const float* __restrict__ expert_w,
                                    const float* __restrict__ gate_w) {
    __shared__ float s[256][10];
    const int bx = blockIdx.x;
    const int d0 = blockIdx.y * 256;
    const int tid = threadIdx.x;
    const float* src = (bx < 10) ? expert_w + (size_t)bx * DDIM * 10
                                 : gate_w   + (size_t)(bx - 10) * DDIM * 10;
    #pragma unroll
    for (int k = 0; k < 10; ++k) {
        int idx = tid + k * 256;                  // coalesced reads
        s[idx / 10][idx % 10] = src[(size_t)d0 * 10 + idx];
    }
    __syncthreads();
    const int j0 = (bx < 10) ? bx * 10 : 100 + (bx - 10) * 10;
    #pragma unroll
    for (int r = 0; r < 10; ++r)                  // coalesced writes
        g_Wpack[(size_t)(j0 + r) * DDIM + d0 + tid] = __float2bfloat16(s[tid][r]);
}

// ---------------- fused MMoE main kernel (128x128, CTA phase skew) -----------
extern "C" __global__ void __launch_bounds__(256, 2)
mmoe_main_kernel(const float* __restrict__ x,
                 const float* __restrict__ expert_b,   // [10,10]
                 const float* __restrict__ gate_b,     // [2,10]
                 const float* __restrict__ ctr_w,      // [10]
                 const float* __restrict__ ctr_b,      // [1]
                 const float* __restrict__ cvr_w,      // [10]
                 const float* __restrict__ cvr_b,      // [1]
                 float* __restrict__ out) {            // [2*B] = [ctr | cvr]
    extern __shared__ char smem[];
    const uint32_t smem_base = smem_u32(smem);
    float* outS = reinterpret_cast<float*>(smem);

    // ---- CTA time-skew: co-resident pair is (b, b+148); 148 % 3 == 1, so
    // bid%3 differs within a pair -> anti-phase the per-chunk pipe bursts.
    {
        const int sk = blockIdx.x % 3;
        if (sk) {
            const long long lim = sk * 1500;
            long long t0 = clock64();
            while (clock64() - t0 < lim) { }
        }
    }

    const int tid  = threadIdx.x;
    const int wid  = tid >> 5;
    const int lane = tid & 31;
    const int gid  = lane >> 2;   // 0..7
    const int tig  = lane & 3;    // 0..3
    const int warp_m = (wid & 3) * 32;    // 4 warps along M (128 rows)
    const int warp_n = (wid >> 2) * 64;   // 2 warps along N (128 cols)
    const int row0 = blockIdx.x * TILE_M;
    const int wstag = wid & 3;            // per-warp kt phase stagger

    // ldmatrix per-lane base byte offsets (within a stage buffer)
    const uint32_t aLdsmBase =
        (uint32_t)(warp_m + ((lane >> 3) & 1) * 8 + (lane & 7)) * (APAD * 2)
        + ((lane >> 4) & 1) * 16;
    const uint32_t bLdsmBase =
        (uint32_t)(warp_n + ((lane >> 4) & 1) * 8 + (lane & 7)) * (APAD * 2)
        + ((lane >> 3) & 1) * 16;

    // load-mapping ids
    const int rbase = tid >> 4;          // A: rows rbase + it*16 (it<8)
    const int c4    = tid & 15;          // col float4
    const int brb   = tid >> 3;          // B: rows brb + it*32 (it<4)
    const int c8    = tid & 7;           // col uint4

    float acc[2][8][4];
    #pragma unroll
    for (int mt = 0; mt < 2; ++mt)
        #pragma unroll
        for (int nt = 0; nt < 8; ++nt)
            #pragma unroll
            for (int i = 0; i < 4; ++i) acc[mt][nt][i] = 0.0f;

    // ---- prologue: prefetch chunk 0 ----
    float4 av[8];
    #pragma unroll
    for (int it = 0; it < 8; ++it)
        av[it] = *reinterpret_cast<const float4*>(
            x + (size_t)(row0 + rbase + it * 16) * DDIM + c4 * 4);
    {
        const uint32_t bb = smem_base + BOFF;         // bbuf[0]
        #pragma unroll
        for (int it = 0; it < 4; ++it)
            CP_ASYNC16(bb + (uint32_t)((brb + it * 32) * APAD + c8 * 8) * 2,
                       g_Wpack + (size_t)(brb + it * 32) * DDIM + c8 * 8);
        CP_COMMIT();
    }

    for (int c = 0; c < NCHUNK; ++c) {
        __nv_bfloat16* Ab = reinterpret_cast<__nv_bfloat16*>(smem + (c & 1) * ABYTES);
        const uint32_t aStage = smem_base + (c & 1) * ABYTES;
        const uint32_t bStage = smem_base + BOFF + (c & 1) * BBYTES;

        // ---- STS: convert prefetched A regs -> abuf[c&1] ----
        #pragma unroll
        for (int it = 0; it < 8; ++it) {
            __nv_bfloat162 lo = __floats2bfloat162_rn(av[it].x, av[it].y);
            __nv_bfloat162 hi = __floats2bfloat162_rn(av[it].z, av[it].w);
            uint2 pk;
            pk.x = *reinterpret_cast<uint32_t*>(&lo);
            pk.y = *reinterpret_cast<uint32_t*>(&hi);
            *reinterpret_cast<uint2*>(Ab + (rbase + it * 16) * APAD + c4 * 4) = pk;
        }

        // ---- prefetch A chunk c+1 into regs ----
        if (c + 1 < NCHUNK) {
            const int k0n = (c + 1) * KC;
            #pragma unroll
            for (int it = 0; it < 8; ++it)
                av[it] = *reinterpret_cast<const float4*>(
                    x + (size_t)(row0 + rbase + it * 16) * DDIM + k0n + c4 * 4);
        }

        CP_WAIT0();          // B(c) landed (overlapped MMA(c-1))
        __syncthreads();     // A(c)/B(c) staged; prev MMAs retired

        // ---- issue B chunk c+1 (buffer free: all warps past MMA(c-1)) ----
        if (c + 1 < NCHUNK) {
            const int k0n = (c + 1) * KC;
            const uint32_t bb = smem_base + BOFF + ((c + 1) & 1) * BBYTES;
            #pragma unroll
            for (int it = 0; it < 4; ++it)
                CP_ASYNC16(bb + (uint32_t)((brb + it * 32) * APAD + c8 * 8) * 2,
                           g_Wpack + (size_t)(brb + it * 32) * DDIM + k0n + c8 * 8);
            CP_COMMIT();
        }

        // ---- compute: 4 k-tiles of 16, per-warp staggered start ----
        #pragma unroll
        for (int j = 0; j < 4; ++j) {
            const int kt = (j + wstag) & 3;
            const uint32_t kOff = (uint32_t)(32 * kt);   // 16 bf16 = 32 bytes

            uint32_t afrag[2][4];
            #pragma unroll
            for (int mt = 0; mt < 2; ++mt)
                LDSM_X4(afrag[mt][0], afrag[mt][1], afrag[mt][2], afrag[mt][3],
                        aStage + aLdsmBase + (uint32_t)(mt * 16 * APAD * 2) + kOff);

            #pragma unroll
            for (int pr = 0; pr < 4; ++pr) {             // four n-group pairs (64 cols)
                uint32_t b0a, b1a, b0b, b1b;
                LDSM_X4(b0a, b1a, b0b, b1b,
                        bStage + bLdsmBase + (uint32_t)(pr * 16 * APAD * 2) + kOff);
                #pragma unroll
                for (int mt = 0; mt < 2; ++mt) {
                    asm volatile(
                        "mma.sync.aligned.m16n8k16.row.col.f32.bf16.bf16.f32 "
                        "{%0,%1,%2,%3}, {%4,%5,%6,%7}, {%8,%9}, {%0,%1,%2,%3};"
                        : "+f"(acc[mt][2 * pr][0]), "+f"(acc[mt][2 * pr][1]),
                          "+f"(acc[mt][2 * pr][2]), "+f"(acc[mt][2 * pr][3])
                        : "r"(afrag[mt][0]), "r"(afrag[mt][1]),
                          "r"(afrag[mt][2]), "r"(afrag[mt][3]),
                          "r"(b0a), "r"(b1a));
                    asm volatile(
                        "mma.sync.aligned.m16n8k16.row.col.f32.bf16.bf16.f32 "
                        "{%0,%1,%2,%3}, {%4,%5,%6,%7}, {%8,%9}, {%0,%1,%2,%3};"
                        : "+f"(acc[mt][2 * pr + 1][0]), "+f"(acc[mt][2 * pr + 1][1]),
                          "+f"(acc[mt][2 * pr + 1][2]), "+f"(acc[mt][2 * pr + 1][3])
                        : "r"(afrag[mt][0]), "r"(afrag[mt][1]),
                          "r"(afrag[mt][2]), "r"(afrag[mt][3]),
                          "r"(b0b), "r"(b1b));
                }
            }
        }
    }
    __syncthreads();   // MMAs done; stage buffers dead -> reuse smem as outS

    // --- scatter accumulators to fp32 out tile ---
    #pragma unroll
    for (int mt = 0; mt < 2; ++mt) {
        #pragma unroll
        for (int nt = 0; nt < 8; ++nt) {
            const int r = warp_m + mt * 16 + gid;
            const int col = warp_n + nt * 8 + tig * 2;
            *reinterpret_cast<float2*>(outS + r * OPAD + col) =
                make_float2(acc[mt][nt][0], acc[mt][nt][1]);
            *reinterpret_cast<float2*>(outS + (r + 8) * OPAD + col) =
                make_float2(acc[mt][nt][2], acc[mt][nt][3]);
        }
    }
    __syncthreads();

    // --- per-row epilogue: softmax gates, expert mix, sigmoid heads ---
    if (tid < TILE_M) {
        const float* rowv = outS + tid * OPAD;

        float g[2][10];
        #pragma unroll
        for (int t = 0; t < 2; ++t) {
            float s = 0.0f;
            #pragma unroll
            for (int e = 0; e < 10; ++e) {
                float l = rowv[100 + t * 10 + e] + gate_b[t * 10 + e];
                float ex = expf(l);
                g[t][e] = ex; s += ex;
            }
            float inv = 1.0f / s;
            #pragma unroll
            for (int e = 0; e < 10; ++e) g[t][e] *= inv;
        }

        float ti0[10], ti1[10];
        #pragma unroll
        for (int u = 0; u < 10; ++u) { ti0[u] = 0.0f; ti1[u] = 0.0f; }
        #pragma unroll
        for (int e = 0; e < 10; ++e) {
            const float g0 = g[0][e], g1 = g[1][e];
            #pragma unroll
            for (int u = 0; u < 10; ++u) {
                const int j = e * 10 + u;
                float v = fmaxf(rowv[j] + expert_b[j], 0.0f);
                ti0[u] += v * g0;
                ti1[u] += v * g1;
            }
        }

        float zc = ctr_b[0], zv = cvr_b[0];
        #pragma unroll
        for (int u = 0; u < 10; ++u) {
            zc += ti0[u] * ctr_w[u];
            zv += ti1[u] * cvr_w[u];
        }
        const int gr = row0 + tid;
        out[gr]         = 1.0f / (1.0f + expf(-zc));
        out[BROWS + gr] = 1.0f / (1.0f + expf(-zv));
    }
}

// ---------------- launch ----------------
extern "C" void kernel_launch(void* const* d_in, const int* in_sizes, int n_in,
                              void* d_out, int out_size) {
    const float* x        = (const float*)d_in[0];
    const float* expert_w = (const float*)d_in[3];
    const float* expert_b = (const float*)d_in[4];
    const float* gate_w   = (const float*)d_in[5];
    const float* gate_b   = (const float*)d_in[6];
    const float* ctr_w    = (const float*)d_in[7];
    const float* ctr_b    = (const float*)d_in[8];
    const float* cvr_w    = (const float*)d_in[9];
    const float* cvr_b    = (const float*)d_in[10];
    float* out = (float*)d_out;

    cudaFuncSetAttribute(mmoe_main_kernel,
                         cudaFuncAttributeMaxDynamicSharedMemorySize, SMEM_BYTES);

    pack_weights_kernel<<<dim3(12, 4), 256>>>(expert_w, gate_w);
    mmoe_main_kernel<<<BROWS / TILE_M, 256, SMEM_BYTES>>>(
        x, expert_b, gate_b, ctr_w, ctr_b, cvr_w, cvr_b, out);
}